// round 15
// baseline (speedup 1.0000x reference)
#include <cuda_runtime.h>

// Problem constants
#define BTOT   100000
#define NNB    16
#define NOB    8
#define SDIM   4
#define HID    64
#define DOBS   85
#define DS_C   0.2f
#define GAM_C  0.01f
#define NB_OFF 5
#define OB_OFF 69

#define REC_STRIDE 144                 // per-sample packed pn2/pn3 record (128B data + 16B pad)
#define REC_BYTES  (256 * REC_STRIDE)  // 36864
#define CHUNK      16                  // bounce chunk (samples)
#define BOUNCE_F   (CHUNK * DOBS)      // 1360 floats
#define DYN_BYTES  (REC_BYTES + BOUNCE_F * 4)   // 42304 B dynamic (+ ~19KB static)

typedef unsigned long long ull;

// ---- packed f32x2 helpers (SASS FFMA2 path) ---------------------------
__device__ __forceinline__ ull pk2(float lo, float hi) {
    ull r; asm("mov.b64 %0,{%1,%2};" : "=l"(r) : "f"(lo), "f"(hi)); return r;
}
__device__ __forceinline__ void up2(ull v, float& lo, float& hi) {
    asm("mov.b64 {%0,%1},%2;" : "=f"(lo), "=f"(hi) : "l"(v));
}
__device__ __forceinline__ ull fma2(ull a, ull b, ull c) {
    ull d; asm("fma.rn.f32x2 %0,%1,%2,%3;" : "=l"(d) : "l"(a), "l"(b), "l"(c)); return d;
}

__global__ __launch_bounds__(256, 3) void barrier_net_kernel(
    const float* __restrict__ x,
    const float* __restrict__ phi_w1, const float* __restrict__ phi_b1,
    const float* __restrict__ phi_w2, const float* __restrict__ phi_b2,
    const float* __restrict__ obs_w1, const float* __restrict__ obs_b1,
    const float* __restrict__ obs_w2, const float* __restrict__ obs_b2,
    const float* __restrict__ rho_w1, const float* __restrict__ rho_b1,
    const float* __restrict__ rho_w2, const float* __restrict__ rho_b2,
    const float* __restrict__ psi_w1, const float* __restrict__ psi_b1,
    const float* __restrict__ psi_w2, const float* __restrict__ psi_b2,
    float* __restrict__ out)
{
    // Dynamic smem: [0, REC_BYTES) per-sample pn2/pn3 records (stride 144B:
    // 36-word stride => 8-lane LDS.128 phases tile all 32 banks, conflict-free);
    // [REC_BYTES, +5440) 16-sample coalescing bounce buffer.
    extern __shared__ __align__(16) char s_dyn[];
    float* s_bounce = (float*)(s_dyn + REC_BYTES);

    // Static smem: weight staging. w1 layers DUPLICATED per hidden unit so
    // one LDS.128 yields two packed (w,w) operands.
    __shared__ __align__(16) float s_phi_w1d[HID * 8];
    __shared__ __align__(8)  float s_phi_b1d[HID * 2];
    __shared__ __align__(16) float s_phi_w2 [HID * 16];
    __shared__ __align__(16) float s_obs_w1d[HID * 4];
    __shared__ __align__(8)  float s_obs_b1d[HID * 2];
    __shared__ __align__(16) float s_obs_w2 [HID * 16];
    __shared__ __align__(16) float s_rho_w1t[HID * 16];   // [j][k]
    __shared__             float s_rho_b1 [HID];
    __shared__ __align__(8)  float s_rho_w2 [HID * 2];
    __shared__ __align__(16) float s_psi_w1t[HID * 4];    // [j][k]={rho0,rho1,g0,g1}
    __shared__             float s_psi_b1 [HID];
    __shared__ __align__(8)  float s_psi_w2 [HID * 2];
    __shared__ __align__(16) float s_accinit[16];
    __shared__             float s_rho_b2 [2];
    __shared__             float s_psi_b2 [2];

    const int tid = threadIdx.x;

    // ---- weight staging (synced by the first chunk barrier below) -----
    for (int i = tid; i < HID * 8; i += 256) {
        int j = i >> 3, c = (i >> 1) & 3;
        s_phi_w1d[i] = phi_w1[c * HID + j];
    }
    for (int i = tid; i < HID * 4; i += 256) {
        int j = i >> 2, c = (i >> 1) & 1;
        s_obs_w1d[i] = obs_w1[c * HID + j];
        int j2 = i >> 2, k2 = i & 3;
        s_psi_w1t[i] = psi_w1[k2 * HID + j2];
    }
    for (int i = tid; i < HID * 2; i += 256) {
        int j = i >> 1;
        s_phi_b1d[i] = phi_b1[j];
        s_obs_b1d[i] = obs_b1[j];
        s_rho_w2[i]  = rho_w2[i];
        s_psi_w2[i]  = psi_w2[i];
    }
    for (int i = tid; i < HID * 16; i += 256) {
        int j = i >> 4, k = i & 15;
        s_rho_w1t[i] = rho_w1[k * HID + j];
        s_phi_w2[i]  = phi_w2[i];
        s_obs_w2[i]  = obs_w2[i];
    }
    for (int i = tid; i < HID; i += 256) {
        s_rho_b1[i] = rho_b1[i];
        s_psi_b1[i] = psi_b1[i];
    }
    if (tid < 16) s_accinit[tid] = (float)NNB * phi_b2[tid] + (float)NOB * obs_b2[tid];
    if (tid < 2)  { s_rho_b2[tid] = rho_b2[tid]; s_psi_b2[tid] = psi_b2[tid]; }

    // ---- chunked coalesced input staging + per-owner repack -----------
    const int base   = blockIdx.x * 256;
    const int nvalid = min(256, BTOT - base);

    ull pn0[8], pn1[8];                   // neighbor components 0,1 (registers)
    #pragma unroll
    for (int p = 0; p < 8; p++) { pn0[p] = 0ull; pn1[p] = 0ull; }
    float bar0 = 0.f, bar1 = 0.f;

    for (int c = 0; c < 16; c++) {
        const int row0  = c * CHUNK;
        const int nrows = max(0, min(CHUNK, nvalid - row0));

        __syncthreads();   // prior chunk's repack done before overwrite
        if (nrows == CHUNK) {
            const float4* src = (const float4*)(x + (long long)(base + row0) * DOBS);
            float4* dst = (float4*)s_bounce;
            for (int i = tid; i < BOUNCE_F / 4; i += 256) dst[i] = src[i];
        } else if (nrows > 0) {
            const float* srcf = x + (long long)(base + row0) * DOBS;
            for (int i = tid; i < nrows * DOBS; i += 256) s_bounce[i] = srcf[i];
        }
        __syncthreads();

        if ((tid >> 4) == c && tid < nvalid) {
            const float* row = s_bounce + (tid & 15) * DOBS;
            ulonglong2* rec = (ulonglong2*)(s_dyn + tid * REC_STRIDE);
            #pragma unroll
            for (int p = 0; p < 8; p++) {
                const float* sp = row + NB_OFF + 8 * p;
                float a0 = sp[0], a1 = sp[1], a2 = sp[2], a3 = sp[3];
                float c0 = sp[4], c1 = sp[5], c2 = sp[6], c3 = sp[7];

                float na = sqrtf(fmaf(a0, a0, a1 * a1));
                float ka = __fdividef(GAM_C, na - DS_C);
                bar0 -= ka * a0;  bar1 -= ka * a1;
                float nc = sqrtf(fmaf(c0, c0, c1 * c1));
                float kc = __fdividef(GAM_C, nc - DS_C);
                bar0 -= kc * c0;  bar1 -= kc * c1;

                pn0[p] = pk2(a0, c0);             // registers
                pn1[p] = pk2(a1, c1);
                ulonglong2 v; v.x = pk2(a2, c2); v.y = pk2(a3, c3);
                rec[p] = v;                        // smem record (own thread only)
            }
        }
    }
    // Records are written and read by the SAME thread — no further syncs.

    const int idx = base + tid;
    if (idx >= BTOT) return;

    // acc packed: accp[t] = (acc_{2t}, acc_{2t+1}); output biases pre-folded
    ull accp[8];
    {
        const ull* ai = (const ull*)s_accinit;
        #pragma unroll
        for (int t = 0; t < 8; t++) accp[t] = ai[t];
    }

    // ---- phi: j outer; pn0/pn1 from regs, pn2/pn3 from smem record ----
    {
        const ulonglong2* rec23 = (const ulonglong2*)(s_dyn + tid * REC_STRIDE);
        const ulonglong2* w1d = (const ulonglong2*)s_phi_w1d;
        const ull*        bdp = (const ull*)s_phi_b1d;
        const ulonglong2* w2p = (const ulonglong2*)s_phi_w2;
        #pragma unroll 2
        for (int j = 0; j < HID; j++) {
            ulonglong2 wa = w1d[2 * j + 0];   // (wx,wx),(wy,wy)
            ulonglong2 wb = w1d[2 * j + 1];   // (wz,wz),(ww,ww)
            ull bb = bdp[j];
            float hsA = 0.f, hsB = 0.f;
            #pragma unroll
            for (int p = 0; p < 8; p++) {
                ulonglong2 v23 = rec23[p];
                ull h = fma2(pn0[p], wa.x, bb);
                h = fma2(pn1[p], wa.y, h);
                h = fma2(v23.x, wb.x, h);
                h = fma2(v23.y, wb.y, h);
                float hx, hy; up2(h, hx, hy);
                hsA += fmaxf(hx, 0.f);
                hsB += fmaxf(hy, 0.f);
            }
            float hsum = hsA + hsB;
            ull hd = pk2(hsum, hsum);
            #pragma unroll
            for (int q = 0; q < 4; q++) {
                ulonglong2 v = w2p[j * 4 + q];
                accp[2 * q + 0] = fma2(hd, v.x, accp[2 * q + 0]);
                accp[2 * q + 1] = fma2(hd, v.y, accp[2 * q + 1]);
            }
        }
    }

    // ---- obs: inputs direct from gmem (18 scalar LDG — small scatter) -
    float g0, g1;
    {
        const float* xr = x + (long long)idx * DOBS;
        ull pm0[4], pm1[4];
        #pragma unroll
        for (int p = 0; p < 4; p++) {
            const float* oa = xr + OB_OFF + 4 * p;
            pm0[p] = pk2(__ldg(oa + 0), __ldg(oa + 2));
            pm1[p] = pk2(__ldg(oa + 1), __ldg(oa + 3));
        }
        g0 = __ldg(xr + 0);  g1 = __ldg(xr + 1);

        const ulonglong2* ow1 = (const ulonglong2*)s_obs_w1d;
        const ull*        obd = (const ull*)s_obs_b1d;
        const ulonglong2* ow2 = (const ulonglong2*)s_obs_w2;
        #pragma unroll 2
        for (int j = 0; j < HID; j++) {
            ulonglong2 w = ow1[j];
            ull bb = obd[j];
            float hsA = 0.f, hsB = 0.f;
            #pragma unroll
            for (int p = 0; p < 4; p++) {
                ull h = fma2(pm0[p], w.x, bb);
                h = fma2(pm1[p], w.y, h);
                float hx, hy; up2(h, hx, hy);
                hsA += fmaxf(hx, 0.f);
                hsB += fmaxf(hy, 0.f);
            }
            float hsum = hsA + hsB;
            ull hd = pk2(hsum, hsum);
            #pragma unroll
            for (int q = 0; q < 4; q++) {
                ulonglong2 v = ow2[j * 4 + q];
                accp[2 * q + 0] = fma2(hd, v.x, accp[2 * q + 0]);
                accp[2 * q + 1] = fma2(hd, v.y, accp[2 * q + 1]);
            }
        }
    }

    // ---- rho: 16 -> 64 -> 2 (packed 16-dot) ---------------------------
    float r0 = s_rho_b2[0], r1 = s_rho_b2[1];
    {
        const ulonglong2* rw = (const ulonglong2*)s_rho_w1t;
        #pragma unroll 2
        for (int j = 0; j < HID; j++) {
            ulonglong2 v0 = rw[4 * j + 0], v1 = rw[4 * j + 1];
            ulonglong2 v2 = rw[4 * j + 2], v3 = rw[4 * j + 3];
            ull hp = fma2(accp[0], v0.x, 0ull);
            hp = fma2(accp[1], v0.y, hp);
            hp = fma2(accp[2], v1.x, hp);
            hp = fma2(accp[3], v1.y, hp);
            hp = fma2(accp[4], v2.x, hp);
            hp = fma2(accp[5], v2.y, hp);
            hp = fma2(accp[6], v3.x, hp);
            hp = fma2(accp[7], v3.y, hp);
            float hx, hy; up2(hp, hx, hy);
            float h = fmaxf(hx + hy + s_rho_b1[j], 0.f);
            r0 = fmaf(h, s_rho_w2[2 * j + 0], r0);
            r1 = fmaf(h, s_rho_w2[2 * j + 1], r1);
        }
    }

    // ---- psi: [rho0,rho1,g0,g1] -> 64 -> 2 ----------------------------
    float e0 = s_psi_b2[0], e1 = s_psi_b2[1];
    {
        ull rg0 = pk2(r0, r1);
        ull rg1 = pk2(g0, g1);
        const ulonglong2* pw = (const ulonglong2*)s_psi_w1t;
        #pragma unroll 4
        for (int j = 0; j < HID; j++) {
            ulonglong2 w = pw[j];   // (wx,wy),(wz,ww)
            ull hp = fma2(rg0, w.x, 0ull);
            hp = fma2(rg1, w.y, hp);
            float hx, hy; up2(hp, hx, hy);
            float h = fmaxf(hx + hy + s_psi_b1[j], 0.f);
            e0 = fmaf(h, s_psi_w2[2 * j + 0], e0);
            e1 = fmaf(h, s_psi_w2[2 * j + 1], e1);
        }
    }

    // empty affine == tanh(e); final affine == 2*action
    float a0 = tanhf(tanhf(e0) + bar0);
    float a1 = tanhf(tanhf(e1) + bar1);
    ((float2*)out)[idx] = make_float2(2.f * a0, 2.f * a1);
}

extern "C" void kernel_launch(void* const* d_in, const int* in_sizes, int n_in,
                              void* d_out, int out_size)
{
    const float* x       = (const float*)d_in[0];
    const float* phi_w1  = (const float*)d_in[1];
    const float* phi_b1  = (const float*)d_in[2];
    const float* phi_w2  = (const float*)d_in[3];
    const float* phi_b2  = (const float*)d_in[4];
    const float* obs_w1  = (const float*)d_in[5];
    const float* obs_b1  = (const float*)d_in[6];
    const float* obs_w2  = (const float*)d_in[7];
    const float* obs_b2  = (const float*)d_in[8];
    const float* rho_w1  = (const float*)d_in[9];
    const float* rho_b1  = (const float*)d_in[10];
    const float* rho_w2  = (const float*)d_in[11];
    const float* rho_b2  = (const float*)d_in[12];
    const float* psi_w1  = (const float*)d_in[13];
    const float* psi_b1  = (const float*)d_in[14];
    const float* psi_w2  = (const float*)d_in[15];
    const float* psi_b2  = (const float*)d_in[16];
    float* out = (float*)d_out;

    // Opt in to >48KB (static+dynamic) smem per block. Runs once, on the
    // first (uncaptured) correctness call — same pattern that passed graph
    // capture in the 61.9us kernel. Not an allocation.
    static bool attr_done = false;
    if (!attr_done) {
        cudaFuncSetAttribute(barrier_net_kernel,
                             cudaFuncAttributeMaxDynamicSharedMemorySize, DYN_BYTES);
        attr_done = true;
    }

    const int grid = (BTOT + 255) / 256;   // 391 — all resident at 3 CTAs/SM
    barrier_net_kernel<<<grid, 256, DYN_BYTES>>>(
        x,
        phi_w1, phi_b1, phi_w2, phi_b2,
        obs_w1, obs_b1, obs_w2, obs_b2,
        rho_w1, rho_b1, rho_w2, rho_b2,
        psi_w1, psi_b1, psi_w2, psi_b2,
        out);
}

// round 16
// speedup vs baseline: 1.8109x; 1.8109x over previous
#include <cuda_runtime.h>

// Problem constants
#define BTOT   100000
#define NNB    16
#define NOB    8
#define SDIM   4
#define HID    64
#define DOBS   85
#define DS_C   0.2f
#define GAM_C  0.01f
#define NB_OFF 5
#define OB_OFF 69

typedef unsigned long long ull;

// ---- packed f32x2 helpers (SASS FFMA2 path) ---------------------------
__device__ __forceinline__ ull pk2(float lo, float hi) {
    ull r; asm("mov.b64 %0,{%1,%2};" : "=l"(r) : "f"(lo), "f"(hi)); return r;
}
__device__ __forceinline__ void up2(ull v, float& lo, float& hi) {
    asm("mov.b64 {%0,%1},%2;" : "=f"(lo), "=f"(hi) : "l"(v));
}
__device__ __forceinline__ ull fma2(ull a, ull b, ull c) {
    ull d; asm("fma.rn.f32x2 %0,%1,%2,%3;" : "=l"(d) : "l"(a), "l"(b), "l"(c)); return d;
}
__device__ __forceinline__ ull add2(ull a, ull b) {
    ull d; asm("add.rn.f32x2 %0,%1,%2;" : "=l"(d) : "l"(a), "l"(b)); return d;
}

__global__ __launch_bounds__(256, 2) void barrier_net_kernel(
    const float* __restrict__ x,
    const float* __restrict__ phi_w1, const float* __restrict__ phi_b1,
    const float* __restrict__ phi_w2, const float* __restrict__ phi_b2,
    const float* __restrict__ obs_w1, const float* __restrict__ obs_b1,
    const float* __restrict__ obs_w2, const float* __restrict__ obs_b2,
    const float* __restrict__ rho_w1, const float* __restrict__ rho_b1,
    const float* __restrict__ rho_w2, const float* __restrict__ rho_b2,
    const float* __restrict__ psi_w1, const float* __restrict__ psi_b1,
    const float* __restrict__ psi_w2, const float* __restrict__ psi_b2,
    float* __restrict__ out)
{
    // Dynamic smem: this block's 256 x-rows (87040 B), loaded COALESCED.
    // Row stride 85 floats: gcd(85,32)=1 => conflict-free per-thread reads.
    extern __shared__ float s_x[];

    __shared__ __align__(16) float s_phi_w1d[HID * 8];
    __shared__ __align__(8)  float s_phi_b1d[HID * 2];
    __shared__ __align__(16) float s_phi_w2 [HID * 16];
    __shared__ __align__(16) float s_obs_w1d[HID * 4];
    __shared__ __align__(8)  float s_obs_b1d[HID * 2];
    __shared__ __align__(16) float s_obs_w2 [HID * 16];
    __shared__ __align__(16) float s_rho_w1t[HID * 16];   // [j][k]
    __shared__             float s_rho_b1 [HID];
    __shared__ __align__(8)  float s_rho_w2 [HID * 2];
    __shared__ __align__(16) float s_psi_w1t[HID * 4];    // [j][k]={rho0,rho1,g0,g1}
    __shared__             float s_psi_b1 [HID];
    __shared__ __align__(8)  float s_psi_w2 [HID * 2];
    __shared__ __align__(16) float s_accinit[16];
    __shared__             float s_rho_b2 [2];
    __shared__             float s_psi_b2 [2];

    const int tid = threadIdx.x;

    // ---- coalesced x staging: gmem -> smem (float4) -------------------
    {
        const int base = blockIdx.x * 256;
        const int nrows = min(256, BTOT - base);
        const int nf4 = nrows * DOBS / 4;                 // 85*nrows % 4 == 0
        const float4* src = (const float4*)(x + (long long)base * DOBS);
        float4* dst = (float4*)s_x;
        for (int i = tid; i < nf4; i += 256) dst[i] = src[i];
    }

    // ---- weight staging ----------------------------------------------
    for (int i = tid; i < HID * 8; i += 256) {
        int j = i >> 3, c = (i >> 1) & 3;
        s_phi_w1d[i] = phi_w1[c * HID + j];
    }
    for (int i = tid; i < HID * 4; i += 256) {
        int j = i >> 2, c = (i >> 1) & 1;
        s_obs_w1d[i] = obs_w1[c * HID + j];
        int j2 = i >> 2, k2 = i & 3;
        s_psi_w1t[i] = psi_w1[k2 * HID + j2];
    }
    for (int i = tid; i < HID * 2; i += 256) {
        int j = i >> 1;
        s_phi_b1d[i] = phi_b1[j];
        s_obs_b1d[i] = obs_b1[j];
        s_rho_w2[i]  = rho_w2[i];
        s_psi_w2[i]  = psi_w2[i];
    }
    for (int i = tid; i < HID * 16; i += 256) {
        int j = i >> 4, k = i & 15;
        s_rho_w1t[i] = rho_w1[k * HID + j];
        s_phi_w2[i]  = phi_w2[i];
        s_obs_w2[i]  = obs_w2[i];
    }
    for (int i = tid; i < HID; i += 256) {
        s_rho_b1[i] = rho_b1[i];
        s_psi_b1[i] = psi_b1[i];
    }
    if (tid < 16) s_accinit[tid] = (float)NNB * phi_b2[tid] + (float)NOB * obs_b2[tid];
    if (tid < 2)  { s_rho_b2[tid] = rho_b2[tid]; s_psi_b2[tid] = psi_b2[tid]; }
    __syncthreads();

    const int idx = blockIdx.x * 256 + tid;
    if (idx >= BTOT) return;   // after the sync; no further block syncs

    const float* xr = s_x + tid * DOBS;   // conflict-free smem row

    // ---- stage neighbors packed in pairs; barrier on the fly ----------
    ull pn0[8], pn1[8], pn2[8], pn3[8];
    float bar0 = 0.f, bar1 = 0.f;
    #pragma unroll
    for (int p = 0; p < 8; p++) {
        const float* sp = xr + NB_OFF + (2 * p) * SDIM;
        float a0 = sp[0], a1 = sp[1], a2 = sp[2], a3 = sp[3];
        float c0 = sp[4], c1 = sp[5], c2 = sp[6], c3 = sp[7];

        float na = sqrtf(fmaf(a0, a0, a1 * a1));
        float ka = GAM_C / (na - DS_C);
        bar0 -= ka * a0;  bar1 -= ka * a1;
        float nc = sqrtf(fmaf(c0, c0, c1 * c1));
        float kc = GAM_C / (nc - DS_C);
        bar0 -= kc * c0;  bar1 -= kc * c1;

        pn0[p] = pk2(a0, c0);
        pn1[p] = pk2(a1, c1);
        pn2[p] = pk2(a2, c2);
        pn3[p] = pk2(a3, c3);
    }
    ull pm0[4], pm1[4];
    #pragma unroll
    for (int p = 0; p < 4; p++) {
        const float* oa = xr + OB_OFF + 4 * p;
        pm0[p] = pk2(oa[0], oa[2]);
        pm1[p] = pk2(oa[1], oa[3]);
    }
    float g0 = xr[0], g1 = xr[1];

    // acc packed: accp[t] = (acc_{2t}, acc_{2t+1}); output biases pre-folded
    ull accp[8];
    {
        const ull* ai = (const ull*)s_accinit;
        #pragma unroll
        for (int t = 0; t < 8; t++) accp[t] = ai[t];
    }

    // ---- phi: j outer; software-pipelined weights, 4-way relu-sum -----
    {
        const ulonglong2* w1d = (const ulonglong2*)s_phi_w1d;
        const ull*        bdp = (const ull*)s_phi_b1d;
        const ulonglong2* w2p = (const ulonglong2*)s_phi_w2;
        ulonglong2 wa = w1d[0];
        ulonglong2 wb = w1d[1];
        ull        bb = bdp[0];
        #pragma unroll 2
        for (int j = 0; j < HID; j++) {
            // prefetch next j's weights before the dependent chain
            ulonglong2 wa_n, wb_n; ull bb_n;
            if (j + 1 < HID) {
                wa_n = w1d[2 * (j + 1) + 0];
                wb_n = w1d[2 * (j + 1) + 1];
                bb_n = bdp[j + 1];
            }
            float hs0 = 0.f, hs1 = 0.f, hs2 = 0.f, hs3 = 0.f;
            #pragma unroll
            for (int p = 0; p < 8; p += 2) {
                ull hA = fma2(pn0[p], wa.x, bb);
                ull hB = fma2(pn0[p + 1], wa.x, bb);
                hA = fma2(pn1[p], wa.y, hA);
                hB = fma2(pn1[p + 1], wa.y, hB);
                hA = fma2(pn2[p], wb.x, hA);
                hB = fma2(pn2[p + 1], wb.x, hB);
                hA = fma2(pn3[p], wb.y, hA);
                hB = fma2(pn3[p + 1], wb.y, hB);
                float ax, ay, bx, by;
                up2(hA, ax, ay); up2(hB, bx, by);
                hs0 += fmaxf(ax, 0.f);
                hs1 += fmaxf(ay, 0.f);
                hs2 += fmaxf(bx, 0.f);
                hs3 += fmaxf(by, 0.f);
            }
            float hsum = (hs0 + hs1) + (hs2 + hs3);
            ull hd = pk2(hsum, hsum);
            #pragma unroll
            for (int q = 0; q < 4; q++) {
                ulonglong2 v = w2p[j * 4 + q];
                accp[2 * q + 0] = fma2(hd, v.x, accp[2 * q + 0]);
                accp[2 * q + 1] = fma2(hd, v.y, accp[2 * q + 1]);
            }
            wa = wa_n; wb = wb_n; bb = bb_n;
        }
    }

    // ---- obs: j outer; pipelined, dual partials -----------------------
    {
        const ulonglong2* ow1 = (const ulonglong2*)s_obs_w1d;
        const ull*        obd = (const ull*)s_obs_b1d;
        const ulonglong2* ow2 = (const ulonglong2*)s_obs_w2;
        ulonglong2 w = ow1[0];
        ull        bb = obd[0];
        #pragma unroll 2
        for (int j = 0; j < HID; j++) {
            ulonglong2 w_n; ull bb_n;
            if (j + 1 < HID) { w_n = ow1[j + 1]; bb_n = obd[j + 1]; }
            float hs0 = 0.f, hs1 = 0.f, hs2 = 0.f, hs3 = 0.f;
            #pragma unroll
            for (int p = 0; p < 4; p += 2) {
                ull hA = fma2(pm0[p], w.x, bb);
                ull hB = fma2(pm0[p + 1], w.x, bb);
                hA = fma2(pm1[p], w.y, hA);
                hB = fma2(pm1[p + 1], w.y, hB);
                float ax, ay, bx, by;
                up2(hA, ax, ay); up2(hB, bx, by);
                hs0 += fmaxf(ax, 0.f);
                hs1 += fmaxf(ay, 0.f);
                hs2 += fmaxf(bx, 0.f);
                hs3 += fmaxf(by, 0.f);
            }
            float hsum = (hs0 + hs1) + (hs2 + hs3);
            ull hd = pk2(hsum, hsum);
            #pragma unroll
            for (int q = 0; q < 4; q++) {
                ulonglong2 v = ow2[j * 4 + q];
                accp[2 * q + 0] = fma2(hd, v.x, accp[2 * q + 0]);
                accp[2 * q + 1] = fma2(hd, v.y, accp[2 * q + 1]);
            }
            w = w_n; bb = bb_n;
        }
    }

    // ---- rho: 16 -> 64 -> 2 (dual packed chains + prefetch) -----------
    float r0 = s_rho_b2[0], r1 = s_rho_b2[1];
    {
        const ulonglong2* rw = (const ulonglong2*)s_rho_w1t;
        ulonglong2 v0 = rw[0], v1 = rw[1], v2 = rw[2], v3 = rw[3];
        #pragma unroll 2
        for (int j = 0; j < HID; j++) {
            ulonglong2 n0, n1, n2, n3;
            if (j + 1 < HID) {
                n0 = rw[4 * (j + 1) + 0]; n1 = rw[4 * (j + 1) + 1];
                n2 = rw[4 * (j + 1) + 2]; n3 = rw[4 * (j + 1) + 3];
            }
            ull hp = fma2(accp[0], v0.x, 0ull);
            ull hq = fma2(accp[1], v0.y, 0ull);
            hp = fma2(accp[2], v1.x, hp);
            hq = fma2(accp[3], v1.y, hq);
            hp = fma2(accp[4], v2.x, hp);
            hq = fma2(accp[5], v2.y, hq);
            hp = fma2(accp[6], v3.x, hp);
            hq = fma2(accp[7], v3.y, hq);
            hp = add2(hp, hq);
            float hx, hy; up2(hp, hx, hy);
            float h = fmaxf(hx + hy + s_rho_b1[j], 0.f);
            r0 = fmaf(h, s_rho_w2[2 * j + 0], r0);
            r1 = fmaf(h, s_rho_w2[2 * j + 1], r1);
            v0 = n0; v1 = n1; v2 = n2; v3 = n3;
        }
    }

    // ---- psi: [rho0,rho1,g0,g1] -> 64 -> 2 ----------------------------
    float e0 = s_psi_b2[0], e1 = s_psi_b2[1];
    {
        ull rg0 = pk2(r0, r1);
        ull rg1 = pk2(g0, g1);
        const ulonglong2* pw = (const ulonglong2*)s_psi_w1t;
        #pragma unroll 4
        for (int j = 0; j < HID; j++) {
            ulonglong2 w = pw[j];   // (wx,wy),(wz,ww)
            ull hp = fma2(rg0, w.x, 0ull);
            hp = fma2(rg1, w.y, hp);
            float hx, hy; up2(hp, hx, hy);
            float h = fmaxf(hx + hy + s_psi_b1[j], 0.f);
            e0 = fmaf(h, s_psi_w2[2 * j + 0], e0);
            e1 = fmaf(h, s_psi_w2[2 * j + 1], e1);
        }
    }

    // empty affine == tanh(e); final affine == 2*action
    float a0 = tanhf(tanhf(e0) + bar0);
    float a1 = tanhf(tanhf(e1) + bar1);
    ((float2*)out)[idx] = make_float2(2.f * a0, 2.f * a1);
}

extern "C" void kernel_launch(void* const* d_in, const int* in_sizes, int n_in,
                              void* d_out, int out_size)
{
    const float* x       = (const float*)d_in[0];
    const float* phi_w1  = (const float*)d_in[1];
    const float* phi_b1  = (const float*)d_in[2];
    const float* phi_w2  = (const float*)d_in[3];
    const float* phi_b2  = (const float*)d_in[4];
    const float* obs_w1  = (const float*)d_in[5];
    const float* obs_b1  = (const float*)d_in[6];
    const float* obs_w2  = (const float*)d_in[7];
    const float* obs_b2  = (const float*)d_in[8];
    const float* rho_w1  = (const float*)d_in[9];
    const float* rho_b1  = (const float*)d_in[10];
    const float* rho_w2  = (const float*)d_in[11];
    const float* rho_b2  = (const float*)d_in[12];
    const float* psi_w1  = (const float*)d_in[13];
    const float* psi_b1  = (const float*)d_in[14];
    const float* psi_w2  = (const float*)d_in[15];
    const float* psi_b2  = (const float*)d_in[16];
    float* out = (float*)d_out;

    const int dyn_smem = 256 * DOBS * sizeof(float);   // 87040 B
    static bool attr_done = false;
    if (!attr_done) {
        cudaFuncSetAttribute(barrier_net_kernel,
                             cudaFuncAttributeMaxDynamicSharedMemorySize, dyn_smem);
        attr_done = true;
    }

    const int grid = (BTOT + 255) / 256;   // 391
    barrier_net_kernel<<<grid, 256, dyn_smem>>>(
        x,
        phi_w1, phi_b1, phi_w2, phi_b2,
        obs_w1, obs_b1, obs_w2, obs_b2,
        rho_w1, rho_b1, rho_w2, rho_b2,
        psi_w1, psi_b1, psi_w2, psi_b2,
        out);
}